// round 3
// baseline (speedup 1.0000x reference)
#include <cuda_runtime.h>
#include <math.h>

typedef unsigned long long u64;

// ---------------- device globals (scratch; no allocation allowed) ----------
#define MMB 512
__device__ float    g_pmin[MMB];
__device__ float    g_pmax[MMB];
__device__ float    g_min;
__device__ float    g_max;
__device__ double   g_sum;
__device__ unsigned g_cnt = 0;

// ---------------- constants -------------------------------------------------
#define IMG_H 512
#define IMG_W 512
#define N_IMG 48            // B*C = 16*3
#define OUT_H 502
#define OUT_W 502
#define NSTRIPS 3
#define RSTRIP 168          // output rows per CTA (3*168 >= 502)
#define VBW 528             // padded smem row width (cols)

// Gaussian 11-tap weights (sigma=1.5, normalized)
#define GW0 0.00102838f
#define GW1 0.00759877f
#define GW2 0.03600077f
#define GW3 0.10936069f
#define GW4 0.21300553f
#define GW5 0.26601173f

__device__ __constant__ float WS[11] = {GW0, GW1, GW2, GW3, GW4, GW5,
                                        GW4, GW3, GW2, GW1, GW0};

// ---------------- packed f32x2 helpers (sm_103a) -----------------------------
__device__ __forceinline__ u64 pk2(float lo, float hi) {
    u64 r; asm("mov.b64 %0, {%1, %2};" : "=l"(r) : "f"(lo), "f"(hi)); return r;
}
__device__ __forceinline__ void upk2(u64 v, float& lo, float& hi) {
    asm("mov.b64 {%0, %1}, %2;" : "=f"(lo), "=f"(hi) : "l"(v));
}
__device__ __forceinline__ u64 fma2(u64 a, u64 b, u64 c) {
    u64 d; asm("fma.rn.f32x2 %0, %1, %2, %3;" : "=l"(d) : "l"(a), "l"(b), "l"(c));
    return d;
}
__device__ __forceinline__ u64 mul2(u64 a, u64 b) {
    u64 d; asm("mul.rn.f32x2 %0, %1, %2;" : "=l"(d) : "l"(a), "l"(b));
    return d;
}

// ---------------- kernel 1: per-block min/max partials -----------------------
__global__ void minmax_part_kernel(const float4* __restrict__ x, int n4) {
    float vmin = INFINITY, vmax = -INFINITY;
    for (int i = blockIdx.x * blockDim.x + threadIdx.x; i < n4;
         i += gridDim.x * blockDim.x) {
        float4 v = x[i];
        vmin = fminf(vmin, fminf(fminf(v.x, v.y), fminf(v.z, v.w)));
        vmax = fmaxf(vmax, fmaxf(fmaxf(v.x, v.y), fmaxf(v.z, v.w)));
    }
    #pragma unroll
    for (int o = 16; o > 0; o >>= 1) {
        vmin = fminf(vmin, __shfl_down_sync(0xffffffffu, vmin, o));
        vmax = fmaxf(vmax, __shfl_down_sync(0xffffffffu, vmax, o));
    }
    __shared__ float smin[8], smax[8];
    int lane = threadIdx.x & 31, wid = threadIdx.x >> 5;
    if (lane == 0) { smin[wid] = vmin; smax[wid] = vmax; }
    __syncthreads();
    if (wid == 0) {
        vmin = (lane < 8) ? smin[lane] : INFINITY;
        vmax = (lane < 8) ? smax[lane] : -INFINITY;
        #pragma unroll
        for (int o = 4; o > 0; o >>= 1) {
            vmin = fminf(vmin, __shfl_down_sync(0xffffffffu, vmin, o));
            vmax = fmaxf(vmax, __shfl_down_sync(0xffffffffu, vmax, o));
        }
        if (lane == 0) { g_pmin[blockIdx.x] = vmin; g_pmax[blockIdx.x] = vmax; }
    }
}

// ---------------- kernel 2: reduce partials + init sum -----------------------
__global__ void minmax_reduce_kernel() {
    int tid = threadIdx.x;           // 512 threads
    float vmin = g_pmin[tid];
    float vmax = g_pmax[tid];
    #pragma unroll
    for (int o = 16; o > 0; o >>= 1) {
        vmin = fminf(vmin, __shfl_down_sync(0xffffffffu, vmin, o));
        vmax = fmaxf(vmax, __shfl_down_sync(0xffffffffu, vmax, o));
    }
    __shared__ float smin[16], smax[16];
    int lane = tid & 31, wid = tid >> 5;
    if (lane == 0) { smin[wid] = vmin; smax[wid] = vmax; }
    __syncthreads();
    if (tid == 0) {
        float mn = smin[0], mx = smax[0];
        #pragma unroll
        for (int i = 1; i < 16; i++) {
            mn = fminf(mn, smin[i]);
            mx = fmaxf(mx, smax[i]);
        }
        g_min = mn;
        g_max = mx;
        g_sum = 0.0;
    }
}

// ---------------- kernel 3: row-streaming packed-FMA SSIM --------------------
__global__ __launch_bounds__(512, 1)
void ssim_stream_kernel(const float* __restrict__ xg,
                        const float* __restrict__ yg,
                        float* __restrict__ out) {
    // smem: 4 buffered rows of packed vertical results
    __shared__ u64   smAB[4 * VBW];   // (mu1_v, mu2_v) packed
    __shared__ u64   smQQ[4 * VBW];   // (xx_v,  yy_v)  packed
    __shared__ float smC [4 * VBW];   // xy_v scalar
    __shared__ float warp_part[16];

    const int tid   = threadIdx.x;
    const int strip = blockIdx.x;
    const int img   = blockIdx.y;
    const int rows_base = strip * RSTRIP;
    const int nrows     = min(RSTRIP, OUT_H - rows_base);
    const int ngroups   = (nrows + 3) >> 2;

    const float* __restrict__ xi = xg + (size_t)img * (IMG_H * IMG_W);
    const float* __restrict__ yi = yg + (size_t)img * (IMG_H * IMG_W);

    const float L  = g_max - g_min;
    const float C1 = (0.01f * L) * (0.01f * L);
    const float C2 = (0.03f * L) * (0.03f * L);

    // packed tap weights (w, w)
    u64 W2[11];
    #pragma unroll
    for (int k = 0; k < 11; k++) W2[k] = pk2(WS[k], WS[k]);

    // rolling vertical accumulators
    u64 pA[11], pQ[11];
    float sC[11];
    #pragma unroll
    for (int j = 0; j < 11; j++) { pA[j] = 0ull; pQ[j] = 0ull; sC[j] = 0.0f; }

    // ---- prologue: input rows 0..9 (no flush, always in-bounds) ----
    #pragma unroll 2
    for (int i = 0; i < 10; i++) {
        int idx = (rows_base + i) * IMG_W + tid;
        float x = xi[idx], y = yi[idx];
        u64 pxy = pk2(x, y);
        u64 pqq = mul2(pxy, pxy);
        float xy = x * y;
        #pragma unroll
        for (int j = 0; j < 11; j++) {
            pA[j] = fma2(W2[10 - j], pxy, pA[j]);
            pQ[j] = fma2(W2[10 - j], pqq, pQ[j]);
            sC[j] = fmaf(WS[10 - j], xy, sC[j]);
        }
        #pragma unroll
        for (int j = 0; j < 10; j++) {
            pA[j] = pA[j + 1]; pQ[j] = pQ[j + 1]; sC[j] = sC[j + 1];
        }
        pA[10] = 0ull; pQ[10] = 0ull; sC[10] = 0.0f;
    }

    const int hrow = tid >> 7;          // 0..3
    const int c0   = (tid & 127) * 4;   // 0..508
    float tsum = 0.0f;

    // preload group 0 input rows (always in-bounds)
    float xv[4], yv[4];
    #pragma unroll
    for (int s = 0; s < 4; s++) {
        int idx = (rows_base + 10 + s) * IMG_W + tid;
        xv[s] = xi[idx];
        yv[s] = yi[idx];
    }

    for (int g = 0; g < ngroups; g++) {
        // ---- vertical FIR update + flush 4 rows ----
        #pragma unroll
        for (int s = 0; s < 4; s++) {
            float x = xv[s], y = yv[s];
            u64 pxy = pk2(x, y);
            u64 pqq = mul2(pxy, pxy);
            float xy = x * y;
            #pragma unroll
            for (int j = 0; j < 11; j++) {
                pA[j] = fma2(W2[10 - j], pxy, pA[j]);
                pQ[j] = fma2(W2[10 - j], pqq, pQ[j]);
                sC[j] = fmaf(WS[10 - j], xy, sC[j]);
            }
            smAB[s * VBW + tid] = pA[0];
            smQQ[s * VBW + tid] = pQ[0];
            smC [s * VBW + tid] = sC[0];
            #pragma unroll
            for (int j = 0; j < 10; j++) {
                pA[j] = pA[j + 1]; pQ[j] = pQ[j + 1]; sC[j] = sC[j + 1];
            }
            pA[10] = 0ull; pQ[10] = 0ull; sC[10] = 0.0f;
        }
        __syncthreads();

        // ---- prefetch next group's input rows ----
        if (g + 1 < ngroups) {
            #pragma unroll
            for (int s = 0; s < 4; s++) {
                int gr = rows_base + (g + 1) * 4 + 10 + s;
                bool ok = gr < IMG_H;
                int idx = gr * IMG_W + tid;
                xv[s] = ok ? xi[idx] : 0.0f;
                yv[s] = ok ? yi[idx] : 0.0f;
            }
        }

        // ---- horizontal 11-tap (packed) + SSIM: 4 outputs/thread ----
        float mu1[4], mu2[4], qxx[4], qyy[4], mxy[4];
        {   // map pair (mu1, mu2)
            const ulonglong2* p = (const ulonglong2*)&smAB[hrow * VBW + c0];
            u64 e[14];
            #pragma unroll
            for (int i = 0; i < 7; i++) {
                ulonglong2 q = p[i]; e[2 * i] = q.x; e[2 * i + 1] = q.y;
            }
            #pragma unroll
            for (int off = 0; off < 4; off++) {
                u64 acc = 0ull;
                #pragma unroll
                for (int k = 0; k < 11; k++) acc = fma2(W2[k], e[off + k], acc);
                upk2(acc, mu1[off], mu2[off]);
            }
        }
        {   // map pair (xx, yy)
            const ulonglong2* p = (const ulonglong2*)&smQQ[hrow * VBW + c0];
            u64 e[14];
            #pragma unroll
            for (int i = 0; i < 7; i++) {
                ulonglong2 q = p[i]; e[2 * i] = q.x; e[2 * i + 1] = q.y;
            }
            #pragma unroll
            for (int off = 0; off < 4; off++) {
                u64 acc = 0ull;
                #pragma unroll
                for (int k = 0; k < 11; k++) acc = fma2(W2[k], e[off + k], acc);
                upk2(acc, qxx[off], qyy[off]);
            }
        }
        {   // scalar map (xy)
            const float4* p = (const float4*)&smC[hrow * VBW + c0];
            float4 q0 = p[0], q1 = p[1], q2 = p[2], q3 = p[3];
            float v[16] = {q0.x, q0.y, q0.z, q0.w, q1.x, q1.y, q1.z, q1.w,
                           q2.x, q2.y, q2.z, q2.w, q3.x, q3.y, q3.z, q3.w};
            #pragma unroll
            for (int off = 0; off < 4; off++) {
                float acc = 0.0f;
                #pragma unroll
                for (int k = 0; k < 11; k++) acc = fmaf(WS[k], v[off + k], acc);
                mxy[off] = acc;
            }
        }

        int orow = rows_base + g * 4 + hrow;
        if (orow < OUT_H) {
            #pragma unroll
            for (int off = 0; off < 4; off++) {
                if (c0 + off < OUT_W) {
                    float m1 = mu1[off], m2 = mu2[off];
                    float m1sq = m1 * m1, m2sq = m2 * m2, m12 = m1 * m2;
                    float v1 = 2.0f * (mxy[off] - m12) + C2;
                    float v2 = (qxx[off] - m1sq) + (qyy[off] - m2sq) + C2;
                    float num = (2.0f * m12 + C1) * v1;
                    float den = (m1sq + m2sq + C1) * v2;
                    tsum += __fdividef(num, den);
                }
            }
        }
        __syncthreads();
    }

    // ---- block reduction into global double sum ----
    #pragma unroll
    for (int o = 16; o > 0; o >>= 1)
        tsum += __shfl_down_sync(0xffffffffu, tsum, o);
    int lane = tid & 31, wid = tid >> 5;
    if (lane == 0) warp_part[wid] = tsum;
    __syncthreads();
    if (wid == 0) {
        float v = (lane < 16) ? warp_part[lane] : 0.0f;
        #pragma unroll
        for (int o = 8; o > 0; o >>= 1)
            v += __shfl_down_sync(0xffffffffu, v, o);
        if (lane == 0) atomicAdd(&g_sum, (double)v);
    }

    // ---- fused finalize: last CTA writes the output ----
    if (tid == 0) {
        __threadfence();
        unsigned old = atomicAdd(&g_cnt, 1u);
        if (old == (unsigned)(NSTRIPS * N_IMG) - 1u) {
            g_cnt = 0;
            double total = atomicAdd(&g_sum, 0.0);   // coherent read
            const double n = (double)N_IMG * OUT_H * OUT_W;
            out[0] = (float)(-(total / n));
        }
    }
}

// ---------------- launcher ----------------------------------------------------
extern "C" void kernel_launch(void* const* d_in, const int* in_sizes, int n_in,
                              void* d_out, int out_size) {
    const float* y_pred = (const float*)d_in[0];
    const float* y_true = (const float*)d_in[1];
    float* out = (float*)d_out;

    int n4 = (N_IMG * IMG_H * IMG_W) / 4;
    minmax_part_kernel<<<MMB, 256>>>((const float4*)y_pred, n4);
    minmax_reduce_kernel<<<1, 512>>>();

    dim3 grid(NSTRIPS, N_IMG);
    ssim_stream_kernel<<<grid, 512>>>(y_pred, y_true, out);
}

// round 4
// speedup vs baseline: 1.6550x; 1.6550x over previous
#include <cuda_runtime.h>
#include <math.h>

// ---------------- device globals (scratch; no allocation allowed) ----------
#define MMB 1536
__device__ float    g_pmin[MMB];
__device__ float    g_pmax[MMB];
__device__ float    g_min;
__device__ float    g_max;
__device__ double   g_sum;
__device__ unsigned g_cnt = 0;

// ---------------- constants -------------------------------------------------
#define IMG_H 512
#define IMG_W 512
#define N_IMG 48            // B*C
#define OUT_H 502
#define OUT_W 502
#define NSTRIPS 3
#define RSTRIP 168          // 3*168 >= 502
#define NGROUPS 42          // RSTRIP/4, divisible by 3
#define VBW 528             // padded smem row width

// Gaussian 11-tap weights (sigma=1.5, normalized) as literal macro so every
// fmaf gets the FFMA-imm form (rt_SMSP=1).
#define WW(j) ((j)==0 ? 0.00102838f : \
               (j)==1 ? 0.00759877f : \
               (j)==2 ? 0.03600077f : \
               (j)==3 ? 0.10936069f : \
               (j)==4 ? 0.21300553f : \
               (j)==5 ? 0.26601173f : \
               (j)==6 ? 0.21300553f : \
               (j)==7 ? 0.10936069f : \
               (j)==8 ? 0.03600077f : \
               (j)==9 ? 0.00759877f : 0.00102838f)

// ---------------- kernel 1: per-block min/max partials (MLP=8) ---------------
__global__ __launch_bounds__(256)
void minmax_part_kernel(const float4* __restrict__ x) {
    const int t = blockIdx.x * 256 + threadIdx.x;
    const int stride = MMB * 256;               // 393216
    float4 v[8];
    #pragma unroll
    for (int k = 0; k < 8; k++) v[k] = x[t + k * stride];

    float vmin = INFINITY, vmax = -INFINITY;
    #pragma unroll
    for (int k = 0; k < 8; k++) {
        vmin = fminf(vmin, fminf(fminf(v[k].x, v[k].y), fminf(v[k].z, v[k].w)));
        vmax = fmaxf(vmax, fmaxf(fmaxf(v[k].x, v[k].y), fmaxf(v[k].z, v[k].w)));
    }
    #pragma unroll
    for (int o = 16; o > 0; o >>= 1) {
        vmin = fminf(vmin, __shfl_down_sync(0xffffffffu, vmin, o));
        vmax = fmaxf(vmax, __shfl_down_sync(0xffffffffu, vmax, o));
    }
    __shared__ float smin[8], smax[8];
    int lane = threadIdx.x & 31, wid = threadIdx.x >> 5;
    if (lane == 0) { smin[wid] = vmin; smax[wid] = vmax; }
    __syncthreads();
    if (wid == 0) {
        vmin = (lane < 8) ? smin[lane] : INFINITY;
        vmax = (lane < 8) ? smax[lane] : -INFINITY;
        #pragma unroll
        for (int o = 4; o > 0; o >>= 1) {
            vmin = fminf(vmin, __shfl_down_sync(0xffffffffu, vmin, o));
            vmax = fmaxf(vmax, __shfl_down_sync(0xffffffffu, vmax, o));
        }
        if (lane == 0) { g_pmin[blockIdx.x] = vmin; g_pmax[blockIdx.x] = vmax; }
    }
}

// ---------------- kernel 2: reduce partials + init sum -----------------------
__global__ void minmax_reduce_kernel() {
    int tid = threadIdx.x;           // 512 threads
    float vmin = INFINITY, vmax = -INFINITY;
    #pragma unroll
    for (int k = 0; k < MMB / 512; k++) {
        vmin = fminf(vmin, g_pmin[tid + k * 512]);
        vmax = fmaxf(vmax, g_pmax[tid + k * 512]);
    }
    #pragma unroll
    for (int o = 16; o > 0; o >>= 1) {
        vmin = fminf(vmin, __shfl_down_sync(0xffffffffu, vmin, o));
        vmax = fmaxf(vmax, __shfl_down_sync(0xffffffffu, vmax, o));
    }
    __shared__ float smin[16], smax[16];
    int lane = tid & 31, wid = tid >> 5;
    if (lane == 0) { smin[wid] = vmin; smax[wid] = vmax; }
    __syncthreads();
    if (tid == 0) {
        float mn = smin[0], mx = smax[0];
        #pragma unroll
        for (int i = 1; i < 16; i++) {
            mn = fminf(mn, smin[i]);
            mx = fmaxf(mx, smax[i]);
        }
        g_min = mn;
        g_max = mx;
        g_sum = 0.0;
    }
}

// ---------------- vertical FIR: 4 rows with static mod-12 ring ---------------
// PH = (input-row index) mod 12 of the first of the 4 rows; all acc indices
// are compile-time constants -> zero rotation MOVs.
template<int PH>
__device__ __forceinline__ void vert4(
    const float (&xv)[4], const float (&yv)[4],
    float (&a1)[12], float (&a2)[12], float (&aq)[12], float (&ar)[12],
    float* __restrict__ smA, float* __restrict__ smB,
    float* __restrict__ smQ, float* __restrict__ smR, int tid)
{
    #pragma unroll
    for (int s = 0; s < 4; s++) {
        const int P = (PH + s) % 12;
        float x = xv[s], y = yv[s];
        float q = fmaf(y, y, x * x);
        float r = x * y;
        #pragma unroll
        for (int j = 0; j < 11; j++) {
            const int sl = (P - j + 24) % 12;
            a1[sl] = fmaf(WW(j), x, a1[sl]);
            a2[sl] = fmaf(WW(j), y, a2[sl]);
            aq[sl] = fmaf(WW(j), q, aq[sl]);
            ar[sl] = fmaf(WW(j), r, ar[sl]);
        }
        const int fs = (P + 2) % 12;       // completed out row (c-10) mod 12
        smA[s * VBW + tid] = a1[fs];  a1[fs] = 0.0f;
        smB[s * VBW + tid] = a2[fs];  a2[fs] = 0.0f;
        smQ[s * VBW + tid] = aq[fs];  aq[fs] = 0.0f;
        smR[s * VBW + tid] = ar[fs];  ar[fs] = 0.0f;
    }
}

// ---------------- horizontal 11-tap over one smem map ------------------------
__device__ __forceinline__ void hblur4(const float* __restrict__ sm, int base,
                                       float (&h)[4])
{
    const float4* p = (const float4*)(sm + base);
    float4 q0 = p[0], q1 = p[1], q2 = p[2], q3 = p[3];
    float v[16] = {q0.x, q0.y, q0.z, q0.w, q1.x, q1.y, q1.z, q1.w,
                   q2.x, q2.y, q2.z, q2.w, q3.x, q3.y, q3.z, q3.w};
    #pragma unroll
    for (int off = 0; off < 4; off++) {
        float acc = 0.0f;
        #pragma unroll
        for (int k = 0; k < 11; k++)
            acc = fmaf(WW(k), v[off + k], acc);
        h[off] = acc;
    }
}

// ---------------- one group: vertical + prefetch + horizontal + ssim ---------
template<int PH>
__device__ __forceinline__ void group_body(
    int gg, int rows_base,
    const float* __restrict__ xi, const float* __restrict__ yi,
    float (&xv)[4], float (&yv)[4],
    float (&a1)[12], float (&a2)[12], float (&aq)[12], float (&ar)[12],
    float* __restrict__ smA, float* __restrict__ smB,
    float* __restrict__ smQ, float* __restrict__ smR,
    int tid, int hrow, int c0, float C1, float C2, float& tsum)
{
    vert4<PH>(xv, yv, a1, a2, aq, ar, smA, smB, smQ, smR, tid);
    __syncthreads();

    // prefetch next group's 4 input rows (hidden under horizontal work)
    if (gg + 1 < NGROUPS) {
        #pragma unroll
        for (int s = 0; s < 4; s++) {
            int gr = rows_base + 14 + gg * 4 + s;
            bool ok = gr < IMG_H;
            int idx = gr * IMG_W + tid;
            xv[s] = ok ? xi[idx] : 0.0f;
            yv[s] = ok ? yi[idx] : 0.0f;
        }
    }

    // horizontal + SSIM: 4 outputs per thread
    float h1[4], h2[4], hq[4], hr[4];
    int base = hrow * VBW + c0;
    hblur4(smA, base, h1);
    hblur4(smB, base, h2);
    hblur4(smQ, base, hq);
    hblur4(smR, base, hr);

    int orow = rows_base + gg * 4 + hrow;
    if (orow < OUT_H) {
        #pragma unroll
        for (int off = 0; off < 4; off++) {
            if (c0 + off < OUT_W) {
                float m1 = h1[off], m2 = h2[off];
                float m1sq = m1 * m1;
                float musq = fmaf(m2, m2, m1sq);     // mu1^2 + mu2^2
                float m12  = m1 * m2;
                float v1 = 2.0f * (hr[off] - m12) + C2;
                float v2 = (hq[off] - musq) + C2;
                float num = (2.0f * m12 + C1) * v1;
                float den = (musq + C1) * v2;
                tsum += __fdividef(num, den);
            }
        }
    }
    __syncthreads();
}

// ---------------- kernel 3: row-streaming SSIM (static ring, 4 maps) ---------
__global__ __launch_bounds__(512, 1)
void ssim_stream_kernel(const float* __restrict__ xg,
                        const float* __restrict__ yg,
                        float* __restrict__ out)
{
    __shared__ float smA[4 * VBW], smB[4 * VBW], smQ[4 * VBW], smR[4 * VBW];
    __shared__ float warp_part[16];

    const int tid   = threadIdx.x;
    const int strip = blockIdx.x;
    const int img   = blockIdx.y;
    const int rows_base = strip * RSTRIP;

    const float* __restrict__ xi = xg + (size_t)img * (IMG_H * IMG_W);
    const float* __restrict__ yi = yg + (size_t)img * (IMG_H * IMG_W);

    const float L  = g_max - g_min;
    const float C1 = (0.01f * L) * (0.01f * L);
    const float C2 = (0.03f * L) * (0.03f * L);

    float a1[12], a2[12], aq[12], ar[12];
    #pragma unroll
    for (int j = 0; j < 12; j++) { a1[j] = a2[j] = aq[j] = ar[j] = 0.0f; }

    // ---- prologue: input rows c = 0..9 (slots static, no flush) ----
    {
        float px[10], py[10];
        #pragma unroll
        for (int t = 0; t < 10; t++) {
            int idx = (rows_base + t) * IMG_W + tid;   // always in-bounds
            px[t] = xi[idx];
            py[t] = yi[idx];
        }
        #pragma unroll
        for (int t = 0; t < 10; t++) {
            float x = px[t], y = py[t];
            float q = fmaf(y, y, x * x);
            float r = x * y;
            #pragma unroll
            for (int j = 0; j < 10; j++) {      // only out rows >= 0
                if (j <= t) {
                    const int sl = t - j;       // (c-j) mod 12, c=t<10
                    a1[sl] = fmaf(WW(j), x, a1[sl]);
                    a2[sl] = fmaf(WW(j), y, a2[sl]);
                    aq[sl] = fmaf(WW(j), q, aq[sl]);
                    ar[sl] = fmaf(WW(j), r, ar[sl]);
                }
            }
        }
    }

    const int hrow = tid >> 7;          // 0..3
    const int c0   = (tid & 127) * 4;   // 0..508
    float tsum = 0.0f;

    // preload group 0's input rows c = 10..13 (in-bounds: rows_base<=336)
    float xv[4], yv[4];
    #pragma unroll
    for (int s = 0; s < 4; s++) {
        int idx = (rows_base + 10 + s) * IMG_W + tid;
        xv[s] = xi[idx];
        yv[s] = yi[idx];
    }

    // main loop: 14 macro-iterations x 3 groups (phases 10, 2, 6)
    for (int m = 0; m < NGROUPS / 3; m++) {
        int gg = m * 3;
        group_body<10>(gg + 0, rows_base, xi, yi, xv, yv, a1, a2, aq, ar,
                       smA, smB, smQ, smR, tid, hrow, c0, C1, C2, tsum);
        group_body<2> (gg + 1, rows_base, xi, yi, xv, yv, a1, a2, aq, ar,
                       smA, smB, smQ, smR, tid, hrow, c0, C1, C2, tsum);
        group_body<6> (gg + 2, rows_base, xi, yi, xv, yv, a1, a2, aq, ar,
                       smA, smB, smQ, smR, tid, hrow, c0, C1, C2, tsum);
    }

    // ---- block reduction into global double sum ----
    #pragma unroll
    for (int o = 16; o > 0; o >>= 1)
        tsum += __shfl_down_sync(0xffffffffu, tsum, o);
    int lane = tid & 31, wid = tid >> 5;
    if (lane == 0) warp_part[wid] = tsum;
    __syncthreads();
    if (wid == 0) {
        float v = (lane < 16) ? warp_part[lane] : 0.0f;
        #pragma unroll
        for (int o = 8; o > 0; o >>= 1)
            v += __shfl_down_sync(0xffffffffu, v, o);
        if (lane == 0) atomicAdd(&g_sum, (double)v);
    }

    // ---- fused finalize: last CTA writes the output ----
    if (tid == 0) {
        __threadfence();
        unsigned old = atomicAdd(&g_cnt, 1u);
        if (old == (unsigned)(NSTRIPS * N_IMG) - 1u) {
            g_cnt = 0;
            double total = atomicAdd(&g_sum, 0.0);   // coherent read
            const double n = (double)N_IMG * OUT_H * OUT_W;
            out[0] = (float)(-(total / n));
        }
    }
}

// ---------------- launcher ----------------------------------------------------
extern "C" void kernel_launch(void* const* d_in, const int* in_sizes, int n_in,
                              void* d_out, int out_size) {
    const float* y_pred = (const float*)d_in[0];
    const float* y_true = (const float*)d_in[1];
    float* out = (float*)d_out;

    minmax_part_kernel<<<MMB, 256>>>((const float4*)y_pred);
    minmax_reduce_kernel<<<1, 512>>>();

    dim3 grid(NSTRIPS, N_IMG);
    ssim_stream_kernel<<<grid, 512>>>(y_pred, y_true, out);
}